// round 14
// baseline (speedup 1.0000x reference)
#include <cuda_runtime.h>
#include <math.h>

#define Bq 4
#define Hh 8
#define Tt 4096
#define Dd 64
#define NCc 16
#define WSZc 256

// ---------------- scratch (no allocations allowed) ----------------
__device__ float g_dists[Bq * Hh * NCc * Tt];     // [bh, c, t], 8MB
__device__ int   g_idx[Bq * Hh * NCc * WSZc];     // sorted top-k indices
__device__ int   g_cnt[Bq * Hh * Tt];             // scatter counts
__device__ float g_aux_part[Bq * Hh * Tt / 8];    // per-route-block aux partials

// ---------------- kernel 1: route (+ zero cnt) ----------------
__global__ void route_kernel(const float* __restrict__ k,
                             const float* __restrict__ means) {
    __shared__ float sm[NCc * Dd];
    __shared__ float saux;
    __shared__ float sdl[NCc][8];

    {
        long long gid = (long long)blockIdx.x * blockDim.x + threadIdx.x;
        const long long c4 = (long long)Bq * Hh * Tt / 4;
        if (gid < c4) ((int4*)g_cnt)[gid] = make_int4(0, 0, 0, 0);
    }

    int token0 = blockIdx.x * 8;
    int bh = token0 / Tt;
    int h = bh % Hh;
    const float* mh = means + (size_t)h * NCc * Dd;
    for (int i = threadIdx.x; i < NCc * Dd; i += blockDim.x) sm[i] = mh[i];
    if (threadIdx.x == 0) saux = 0.f;
    __syncthreads();

    int warp = threadIdx.x >> 5, lane = threadIdx.x & 31;
    int token = token0 + warp;
    int t = token & (Tt - 1);

    float2 kv = ((const float2*)(k + (size_t)token * Dd))[lane];
    float ss = kv.x * kv.x + kv.y * kv.y;
#pragma unroll
    for (int o = 16; o; o >>= 1) ss += __shfl_xor_sync(0xffffffffu, ss, o);
    float inv = rsqrtf(ss);
    float2 xv = make_float2(kv.x * inv, kv.y * inv);

    float dl[NCc];
#pragma unroll
    for (int c = 0; c < NCc; c++)
        dl[c] = xv.x * sm[c * Dd + 2 * lane] + xv.y * sm[c * Dd + 2 * lane + 1];
#pragma unroll
    for (int o = 16; o; o >>= 1) {
#pragma unroll
        for (int c = 0; c < NCc; c++)
            dl[c] += __shfl_xor_sync(0xffffffffu, dl[c], o);
    }
    int bestc = 0;
    float bestv = dl[0];
#pragma unroll
    for (int c = 1; c < NCc; c++)
        if (dl[c] > bestv) { bestv = dl[c]; bestc = c; }

    if (lane == 0) {
#pragma unroll
        for (int c = 0; c < NCc; c++) sdl[c][warp] = dl[c];
    }

    float mx = sm[bestc * Dd + 2 * lane];
    float my = sm[bestc * Dd + 2 * lane + 1];
    float ex = xv.x - mx, ey = xv.y - my;
    float e = ex * ex + ey * ey;
#pragma unroll
    for (int o = 16; o; o >>= 1) e += __shfl_xor_sync(0xffffffffu, e, o);
    if (lane == 0) atomicAdd(&saux, e);
    __syncthreads();

    if (threadIdx.x < 128) {
        int c = threadIdx.x >> 3, tt = threadIdx.x & 7;
        int tbase = token0 & (Tt - 1);
        g_dists[((size_t)bh * NCc + c) * Tt + tbase + tt] = sdl[c][tt];
    }
    if (threadIdx.x == 0) g_aux_part[blockIdx.x] = saux;
}

// ---------------- kernel 2: radix-select top-WSZ per (b,h,c) (+ zero out) ----
__device__ __forceinline__ unsigned warp_incl_scan(unsigned v, int lane) {
#pragma unroll
    for (int off = 1; off < 32; off <<= 1) {
        unsigned t = __shfl_up_sync(0xffffffffu, v, off);
        if (lane >= off) v += t;
    }
    return v;
}

__device__ __forceinline__ void find_bin(unsigned* h, unsigned* wsum,
                                         unsigned* s_bin, unsigned* s_k, int tid) {
    int lane = tid & 31, w = tid >> 5;
    unsigned K = *s_k;
    unsigned tot = 0;
#pragma unroll
    for (int r = 0; r < 16; r++) tot += h[tid * 16 + r];
    unsigned p = warp_incl_scan(tot, lane);
    if (lane == 31) wsum[w] = p;
    __syncthreads();
    unsigned off = 0, S = 0;
#pragma unroll
    for (int i = 0; i < 8; i++) {
        unsigned x = wsum[i];
        S += x;
        if (i < w) off += x;
    }
    unsigned above = S - (p + off);
    unsigned run = above;
#pragma unroll
    for (int r = 15; r >= 0; r--) {
        unsigned cc = h[tid * 16 + r];
        run += cc;
        if (run >= K && run - cc < K) {
            *s_bin = (unsigned)(tid * 16 + r);
            *s_k = K - (run - cc);
        }
    }
    __syncthreads();
}

__global__ void __launch_bounds__(256) topk_kernel(float* __restrict__ out) {
    __shared__ unsigned su[Tt];
    __shared__ unsigned h[4096];
    __shared__ unsigned wsum[8];
    __shared__ unsigned s_bin, s_k;
    int tid = threadIdx.x;
    int lane = tid & 31, w = tid >> 5;
    int bhc = blockIdx.x;
    const float* dc = g_dists + (size_t)bhc * Tt;

    {
        float4* o4 = (float4*)out + (size_t)blockIdx.x * 4096;
        for (int i = tid; i < 4096; i += 256)
            o4[i] = make_float4(0.f, 0.f, 0.f, 0.f);
    }

    for (int i = tid; i < Tt; i += 256) {
        unsigned uu = __float_as_uint(dc[i]);
        uu = (uu & 0x80000000u) ? ~uu : (uu | 0x80000000u);
        su[i] = uu;
        h[i] = 0u;
    }
    if (tid == 0) s_k = WSZc;
    __syncthreads();

    for (int i = tid; i < Tt; i += 256) atomicAdd(&h[su[i] >> 20], 1u);
    __syncthreads();
    find_bin(h, wsum, &s_bin, &s_k, tid);
    unsigned b1 = s_bin;
    for (int i = tid; i < 4096; i += 256) h[i] = 0u;
    __syncthreads();

    for (int i = tid; i < Tt; i += 256)
        if ((su[i] >> 20) == b1) atomicAdd(&h[(su[i] >> 8) & 0xFFFu], 1u);
    __syncthreads();
    find_bin(h, wsum, &s_bin, &s_k, tid);
    unsigned b2 = s_bin;
    for (int i = tid; i < 4096; i += 256) h[i] = 0u;
    __syncthreads();

    unsigned hi20 = (b1 << 12) | b2;
    for (int i = tid; i < Tt; i += 256)
        if ((su[i] >> 8) == hi20) atomicAdd(&h[su[i] & 0xFFu], 1u);
    __syncthreads();
    find_bin(h, wsum, &s_bin, &s_k, tid);
    unsigned b3 = s_bin;
    unsigned m = s_k;
    unsigned thr = (b1 << 20) | (b2 << 8) | b3;

    unsigned gt = 0, eq = 0;
    int base = tid * 16;
#pragma unroll
    for (int r = 0; r < 16; r++) {
        unsigned uu = su[base + r];
        gt += (uu > thr);
        eq += (uu == thr);
    }
    unsigned mypack = (gt << 16) | eq;
    unsigned p = warp_incl_scan(mypack, lane);
    if (lane == 31) wsum[w] = p;
    __syncthreads();
    unsigned off = 0;
#pragma unroll
    for (int i = 0; i < 8; i++)
        if (i < w) off += wsum[i];
    unsigned excl = p + off - mypack;
    unsigned gtb = excl >> 16, eqb = excl & 0xFFFFu;
    int bh = bhc >> 4;
#pragma unroll
    for (int r = 0; r < 16; r++) {
        unsigned uu = su[base + r];
        if (uu > thr) {
            unsigned emin = eqb < m ? eqb : m;
            int pos = (int)(gtb + emin);
            g_idx[(size_t)bhc * WSZc + pos] = base + r;
            atomicAdd(&g_cnt[bh * Tt + base + r], 1);
            gtb++;
        } else if (uu == thr) {
            if (eqb < m) {
                int pos = (int)(gtb + eqb);
                g_idx[(size_t)bhc * WSZc + pos] = base + r;
                atomicAdd(&g_cnt[bh * Tt + base + r], 1);
            }
            eqb++;
        }
    }
}

// ---------------- kernel 3: fp16 m16n8k16 tensor-core windowed attention -----
// 512 threads = 16 warps. SMSP-balanced tile permutation: warp w computes
// row-tile t = perm(w) so each SMSP's causal workload sums to exactly 68 units.
__device__ __forceinline__ unsigned pack2h(float lo, float hi) {
    unsigned u;
    asm("cvt.rn.f16x2.f32 %0, %1, %2;" : "=r"(u) : "f"(hi), "f"(lo));
    return u;
}
__device__ __forceinline__ unsigned short f2h(float f) {
    unsigned short h;
    asm("cvt.rn.f16.f32 %0, %1;" : "=h"(h) : "f"(f));
    return h;
}
__device__ __forceinline__ void mma16(float* d, const unsigned* a, uint2 b) {
    asm volatile("mma.sync.aligned.m16n8k16.row.col.f32.f16.f16.f32 "
                 "{%0,%1,%2,%3}, {%4,%5,%6,%7}, {%8,%9}, {%0,%1,%2,%3};"
                 : "+f"(d[0]), "+f"(d[1]), "+f"(d[2]), "+f"(d[3])
                 : "r"(a[0]), "r"(a[1]), "r"(a[2]), "r"(a[3]), "r"(b.x), "r"(b.y));
}

__device__ __forceinline__ void epi_vals(int t, int jc, int nt, int g, int c,
                                         float* s, float& l0, float& l1) {
    int i0 = 16 * t + g, i1 = i0 + 8;
    int j0 = 64 * jc + 8 * nt + 2 * c, j1 = j0 + 1;
    s[0] = (j0 > i0) ? 0.f : (j0 == i0) ? ((i0 == 0) ? 1.f : 0.f) : __expf(s[0] * 0.125f);
    s[1] = (j1 > i0) ? 0.f : (j1 == i0) ? 0.f : __expf(s[1] * 0.125f);
    s[2] = (j0 > i1) ? 0.f : (j0 == i1) ? 0.f : __expf(s[2] * 0.125f);
    s[3] = (j1 > i1) ? 0.f : (j1 == i1) ? 0.f : __expf(s[3] * 0.125f);
    l0 += s[0] + s[1];
    l1 += s[2] + s[3];
}

#define KV_BUF 2048                        // u32 per chunk per operand (fp16)
#define ATTN_SMEM_BYTES (8 * KV_BUF * 4)   // KF[4] + VF[4] = 64KB

__global__ void __launch_bounds__(512, 1) attn_kernel(const float* __restrict__ q,
                                                      const float* __restrict__ k,
                                                      const float* __restrict__ v,
                                                      float* __restrict__ out) {
    extern __shared__ unsigned smu[];  // [KF0..KF3, VF0..VF3]
    __shared__ int sidx[WSZc];

    int tid = threadIdx.x;
    int bhc = blockIdx.x;
    int bh = bhc >> 4;
    int w = tid >> 5, lane = tid & 31;
    int g = lane >> 2, c = lane & 3;

    // SMSP-balanced permutation: quads {0,1,2,3},{7,6,5,4},{8,9,10,11},{15,14,13,12}
    int t = 4 * (w >> 2) + (((w >> 2) & 1) ? (3 - (w & 3)) : (w & 3));

    if (tid < WSZc) sidx[tid] = g_idx[(size_t)bhc * WSZc + tid];
    __syncthreads();

    // ---- staging: threads 0-255 K (normalize in-thread), 256-511 V ----
    if (tid < 256) {
        int gj = sidx[tid];
        int jcc = tid >> 6, r = tid & 63;
        const float4* ks4 = (const float4*)(k + ((size_t)bh * Tt + gj) * Dd);
        unsigned* KF = smu + jcc * KV_BUF;
        int nt = r >> 3, gk = r & 7;
        float4 kv[16];
        float ss = 0.f;
#pragma unroll
        for (int e = 0; e < 16; e++) {
            kv[e] = ks4[e];
            ss += kv[e].x * kv[e].x + kv[e].y * kv[e].y +
                  kv[e].z * kv[e].z + kv[e].w * kv[e].w;
        }
        float inv = rsqrtf(ss);
        // KF B-frag: reg0 = {kn[16ks+2c], kn[16ks+2c+1]}, reg1 = d+8
#pragma unroll
        for (int ks = 0; ks < 4; ks++) {
#pragma unroll
            for (int cc = 0; cc < 4; cc++) {
                int e0 = 4 * ks + (cc >> 1);
                float lo0, hi0, lo1, hi1;
                if (cc & 1) {
                    lo0 = kv[e0].z; hi0 = kv[e0].w;
                    lo1 = kv[e0 + 2].z; hi1 = kv[e0 + 2].w;
                } else {
                    lo0 = kv[e0].x; hi0 = kv[e0].y;
                    lo1 = kv[e0 + 2].x; hi1 = kv[e0 + 2].y;
                }
                unsigned r0 = pack2h(lo0 * inv, hi0 * inv);
                unsigned r1 = pack2h(lo1 * inv, hi1 * inv);
                *(uint2*)&KF[((ks * 8 + nt) * 32 + gk * 4 + cc) * 2] = make_uint2(r0, r1);
            }
        }
    } else {
        int rr = tid - 256;
        int gj = sidx[rr];
        int jcc = rr >> 6, r = rr & 63;
        const float4* vs4 = (const float4*)(v + ((size_t)bh * Tt + gj) * Dd);
        unsigned short* VH = (unsigned short*)(smu + 4 * KV_BUF + jcc * KV_BUF);
        // key r within chunk: kg = r>>4, position-in-16: reg*8 + 2c + p
        int kg = r >> 4, rloc = r & 15;
        int reg = (rloc >> 3) & 1, cc = (rloc & 7) >> 1, p = rloc & 1;
#pragma unroll
        for (int e = 0; e < 16; e++) {
            float4 vv = vs4[e];
            float vals[4] = {vv.x, vv.y, vv.z, vv.w};
#pragma unroll
            for (int j = 0; j < 4; j++) {
                int d = e * 4 + j;
                int nt2 = d >> 3, gv = d & 7;
                int addr32 = ((kg * 8 + nt2) * 32 + gv * 4 + cc) * 2 + reg;
                VH[addr32 * 2 + p] = f2h(vals[j]);
            }
        }
    }

    // ---- Q A-fragments (fp16) into registers (warp w owns tile t) ----
    unsigned A[4][4];
    {
        const float* qb = q + (size_t)bh * Tt * Dd;
        const float* r0 = qb + (size_t)sidx[16 * t + g] * Dd;
        const float* r1 = qb + (size_t)sidx[16 * t + g + 8] * Dd;
#pragma unroll
        for (int ks = 0; ks < 4; ks++) {
            int d0 = 16 * ks + 2 * c;
            A[ks][0] = pack2h(r0[d0], r0[d0 + 1]);
            A[ks][1] = pack2h(r1[d0], r1[d0 + 1]);
            A[ks][2] = pack2h(r0[d0 + 8], r0[d0 + 9]);
            A[ks][3] = pack2h(r1[d0 + 8], r1[d0 + 9]);
        }
    }

    float O[8][4];
#pragma unroll
    for (int nt = 0; nt < 8; nt++)
#pragma unroll
        for (int r = 0; r < 4; r++) O[nt][r] = 0.f;
    float lp[2] = {0.f, 0.f};

    __syncthreads();   // the ONLY mainloop barrier

    for (int jc = 0; jc < 4; jc++) {
        int lim = 2 * t + 1 - 8 * jc;
        if (lim < 0) break;
        const unsigned* KF = smu + jc * KV_BUF;
        const unsigned* VF = smu + 4 * KV_BUF + jc * KV_BUF;

#pragma unroll
        for (int nt = 0; nt < 8; nt += 2) {
            if (nt > lim) break;
            bool two = (nt + 1 <= lim);
            float sa[4] = {0.f, 0.f, 0.f, 0.f};  // nt,   ks 0-1
            float sb[4] = {0.f, 0.f, 0.f, 0.f};  // nt,   ks 2-3
            float sc[4] = {0.f, 0.f, 0.f, 0.f};  // nt+1, ks 0-1
            float sd[4] = {0.f, 0.f, 0.f, 0.f};  // nt+1, ks 2-3
#pragma unroll
            for (int ks = 0; ks < 2; ks++) {
                uint2 b0 = *(const uint2*)&KF[((ks * 8 + nt) * 32 + lane) * 2];
                uint2 b1 = *(const uint2*)&KF[(((ks + 2) * 8 + nt) * 32 + lane) * 2];
                mma16(sa, A[ks], b0);
                mma16(sb, A[ks + 2], b1);
                if (two) {
                    uint2 b2 = *(const uint2*)&KF[((ks * 8 + nt + 1) * 32 + lane) * 2];
                    uint2 b3 = *(const uint2*)&KF[(((ks + 2) * 8 + nt + 1) * 32 + lane) * 2];
                    mma16(sc, A[ks], b2);
                    mma16(sd, A[ks + 2], b3);
                }
            }
#pragma unroll
            for (int r = 0; r < 4; r++) { sa[r] += sb[r]; sc[r] += sd[r]; }

            epi_vals(t, jc, nt, g, c, sa, lp[0], lp[1]);
            if (two) epi_vals(t, jc, nt + 1, g, c, sc, lp[0], lp[1]);
            // else sc stays all-zero -> contributes nothing

            // P 16x16 A-fragment = the two accumulators packed (no shuffles)
            unsigned P[4];
            P[0] = pack2h(sa[0], sa[1]);
            P[1] = pack2h(sa[2], sa[3]);
            P[2] = pack2h(sc[0], sc[1]);
            P[3] = pack2h(sc[2], sc[3]);

            int kg = nt >> 1;
#pragma unroll
            for (int nt2 = 0; nt2 < 8; nt2++) {
                uint2 bv = *(const uint2*)&VF[((kg * 8 + nt2) * 32 + lane) * 2];
                mma16(O[nt2], P, bv);
            }
        }
    }

    // ---- row-sum reduce across quad, normalize, scatter ----
    float rs[2];
#pragma unroll
    for (int hf = 0; hf < 2; hf++) {
        float s = lp[hf];
        s += __shfl_xor_sync(0xffffffffu, s, 1);
        s += __shfl_xor_sync(0xffffffffu, s, 2);
        rs[hf] = 1.f / s;
    }
    {
        float* ob = out + (size_t)bh * Tt * Dd;
        float* o0 = ob + (size_t)sidx[16 * t + g] * Dd;
        float* o1 = ob + (size_t)sidx[16 * t + g + 8] * Dd;
#pragma unroll
        for (int nt2 = 0; nt2 < 8; nt2++) {
            int col = 8 * nt2 + 2 * c;
            atomicAdd(o0 + col, O[nt2][0] * rs[0]);
            atomicAdd(o0 + col + 1, O[nt2][1] * rs[0]);
            atomicAdd(o1 + col, O[nt2][2] * rs[1]);
            atomicAdd(o1 + col + 1, O[nt2][3] * rs[1]);
        }
    }
}

// ---------------- kernel 4: divide by count + aux loss ----------------
__global__ void finalize_kernel(float* out, int out_size) {
    const int n = Bq * Hh * Tt * Dd;
    const int n4 = n / 4;
    int i = blockIdx.x * blockDim.x + threadIdx.x;
    int stride = gridDim.x * blockDim.x;
    for (int p = i; p < n4; p += stride) {
        float4 o = ((float4*)out)[p];
        float cc = (float)g_cnt[p >> 4];
        float inv = 1.f / (cc + 1e-5f);
        o.x *= inv; o.y *= inv; o.z *= inv; o.w *= inv;
        ((float4*)out)[p] = o;
    }
    if (blockIdx.x == 0) {
        __shared__ float sred[256];
        float s = 0.f;
        for (int p = threadIdx.x; p < Bq * Hh * Tt / 8; p += 256) s += g_aux_part[p];
        sred[threadIdx.x] = s;
        __syncthreads();
        for (int off = 128; off; off >>= 1) {
            if (threadIdx.x < off) sred[threadIdx.x] += sred[threadIdx.x + off];
            __syncthreads();
        }
        if (threadIdx.x == 0 && out_size > n)
            out[n] = sred[0] * (1e-4f / (float)n);
    }
}

// ---------------- launch ----------------
extern "C" void kernel_launch(void* const* d_in, const int* in_sizes, int n_in,
                              void* d_out, int out_size) {
    const float* q = (const float*)d_in[0];
    const float* k = (const float*)d_in[1];
    const float* v = (const float*)d_in[2];
    const float* means = (const float*)d_in[3];
    float* out = (float*)d_out;

    cudaFuncSetAttribute(attn_kernel, cudaFuncAttributeMaxDynamicSharedMemorySize,
                         ATTN_SMEM_BYTES);

    route_kernel<<<Bq * Hh * Tt / 8, 256>>>(k, means);
    topk_kernel<<<Bq * Hh * NCc, 256>>>(out);
    attn_kernel<<<Bq * Hh * NCc, 512, ATTN_SMEM_BYTES>>>(q, k, v, out);
    finalize_kernel<<<2048, 256>>>(out, out_size);
}

// round 15
// speedup vs baseline: 1.0225x; 1.0225x over previous
#include <cuda_runtime.h>
#include <math.h>

#define Bq 4
#define Hh 8
#define Tt 4096
#define Dd 64
#define NCc 16
#define WSZc 256

// ---------------- scratch (no allocations allowed) ----------------
__device__ float g_dists[Bq * Hh * NCc * Tt];     // [bh, c, t], 8MB
__device__ int   g_idx[Bq * Hh * NCc * WSZc];     // sorted top-k indices
__device__ int   g_cnt[Bq * Hh * Tt];             // scatter counts
__device__ float g_aux_part[Bq * Hh * Tt / 8];    // per-route-block aux partials

// ---------------- kernel 1: route (+ zero cnt) ----------------
__global__ void route_kernel(const float* __restrict__ k,
                             const float* __restrict__ means) {
    __shared__ float sm[NCc * Dd];
    __shared__ float saux;
    __shared__ float sdl[NCc][8];

    {
        long long gid = (long long)blockIdx.x * blockDim.x + threadIdx.x;
        const long long c4 = (long long)Bq * Hh * Tt / 4;
        if (gid < c4) ((int4*)g_cnt)[gid] = make_int4(0, 0, 0, 0);
    }

    int token0 = blockIdx.x * 8;
    int bh = token0 / Tt;
    int h = bh % Hh;
    const float* mh = means + (size_t)h * NCc * Dd;
    for (int i = threadIdx.x; i < NCc * Dd; i += blockDim.x) sm[i] = mh[i];
    if (threadIdx.x == 0) saux = 0.f;
    __syncthreads();

    int warp = threadIdx.x >> 5, lane = threadIdx.x & 31;
    int token = token0 + warp;
    int t = token & (Tt - 1);

    float2 kv = ((const float2*)(k + (size_t)token * Dd))[lane];
    float ss = kv.x * kv.x + kv.y * kv.y;
#pragma unroll
    for (int o = 16; o; o >>= 1) ss += __shfl_xor_sync(0xffffffffu, ss, o);
    float inv = rsqrtf(ss);
    float2 xv = make_float2(kv.x * inv, kv.y * inv);

    float dl[NCc];
#pragma unroll
    for (int c = 0; c < NCc; c++)
        dl[c] = xv.x * sm[c * Dd + 2 * lane] + xv.y * sm[c * Dd + 2 * lane + 1];
#pragma unroll
    for (int o = 16; o; o >>= 1) {
#pragma unroll
        for (int c = 0; c < NCc; c++)
            dl[c] += __shfl_xor_sync(0xffffffffu, dl[c], o);
    }
    int bestc = 0;
    float bestv = dl[0];
#pragma unroll
    for (int c = 1; c < NCc; c++)
        if (dl[c] > bestv) { bestv = dl[c]; bestc = c; }

    if (lane == 0) {
#pragma unroll
        for (int c = 0; c < NCc; c++) sdl[c][warp] = dl[c];
    }

    float mx = sm[bestc * Dd + 2 * lane];
    float my = sm[bestc * Dd + 2 * lane + 1];
    float ex = xv.x - mx, ey = xv.y - my;
    float e = ex * ex + ey * ey;
#pragma unroll
    for (int o = 16; o; o >>= 1) e += __shfl_xor_sync(0xffffffffu, e, o);
    if (lane == 0) atomicAdd(&saux, e);
    __syncthreads();

    if (threadIdx.x < 128) {
        int c = threadIdx.x >> 3, tt = threadIdx.x & 7;
        int tbase = token0 & (Tt - 1);
        g_dists[((size_t)bh * NCc + c) * Tt + tbase + tt] = sdl[c][tt];
    }
    if (threadIdx.x == 0) g_aux_part[blockIdx.x] = saux;
}

// ---------------- kernel 2: radix-select top-WSZ per (b,h,c) (+ zero out) ----
__device__ __forceinline__ unsigned warp_incl_scan(unsigned v, int lane) {
#pragma unroll
    for (int off = 1; off < 32; off <<= 1) {
        unsigned t = __shfl_up_sync(0xffffffffu, v, off);
        if (lane >= off) v += t;
    }
    return v;
}

__device__ __forceinline__ void find_bin(unsigned* h, unsigned* wsum,
                                         unsigned* s_bin, unsigned* s_k, int tid) {
    int lane = tid & 31, w = tid >> 5;
    unsigned K = *s_k;
    unsigned tot = 0;
#pragma unroll
    for (int r = 0; r < 16; r++) tot += h[tid * 16 + r];
    unsigned p = warp_incl_scan(tot, lane);
    if (lane == 31) wsum[w] = p;
    __syncthreads();
    unsigned off = 0, S = 0;
#pragma unroll
    for (int i = 0; i < 8; i++) {
        unsigned x = wsum[i];
        S += x;
        if (i < w) off += x;
    }
    unsigned above = S - (p + off);
    unsigned run = above;
#pragma unroll
    for (int r = 15; r >= 0; r--) {
        unsigned cc = h[tid * 16 + r];
        run += cc;
        if (run >= K && run - cc < K) {
            *s_bin = (unsigned)(tid * 16 + r);
            *s_k = K - (run - cc);
        }
    }
    __syncthreads();
}

__global__ void __launch_bounds__(256) topk_kernel(float* __restrict__ out) {
    __shared__ unsigned su[Tt];
    __shared__ unsigned h[4096];
    __shared__ unsigned wsum[8];
    __shared__ unsigned s_bin, s_k;
    int tid = threadIdx.x;
    int lane = tid & 31, w = tid >> 5;
    int bhc = blockIdx.x;
    const float* dc = g_dists + (size_t)bhc * Tt;

    {
        float4* o4 = (float4*)out + (size_t)blockIdx.x * 4096;
        for (int i = tid; i < 4096; i += 256)
            o4[i] = make_float4(0.f, 0.f, 0.f, 0.f);
    }

    for (int i = tid; i < Tt; i += 256) {
        unsigned uu = __float_as_uint(dc[i]);
        uu = (uu & 0x80000000u) ? ~uu : (uu | 0x80000000u);
        su[i] = uu;
        h[i] = 0u;
    }
    if (tid == 0) s_k = WSZc;
    __syncthreads();

    for (int i = tid; i < Tt; i += 256) atomicAdd(&h[su[i] >> 20], 1u);
    __syncthreads();
    find_bin(h, wsum, &s_bin, &s_k, tid);
    unsigned b1 = s_bin;
    for (int i = tid; i < 4096; i += 256) h[i] = 0u;
    __syncthreads();

    for (int i = tid; i < Tt; i += 256)
        if ((su[i] >> 20) == b1) atomicAdd(&h[(su[i] >> 8) & 0xFFFu], 1u);
    __syncthreads();
    find_bin(h, wsum, &s_bin, &s_k, tid);
    unsigned b2 = s_bin;
    for (int i = tid; i < 4096; i += 256) h[i] = 0u;
    __syncthreads();

    unsigned hi20 = (b1 << 12) | b2;
    for (int i = tid; i < Tt; i += 256)
        if ((su[i] >> 8) == hi20) atomicAdd(&h[su[i] & 0xFFu], 1u);
    __syncthreads();
    find_bin(h, wsum, &s_bin, &s_k, tid);
    unsigned b3 = s_bin;
    unsigned m = s_k;
    unsigned thr = (b1 << 20) | (b2 << 8) | b3;

    unsigned gt = 0, eq = 0;
    int base = tid * 16;
#pragma unroll
    for (int r = 0; r < 16; r++) {
        unsigned uu = su[base + r];
        gt += (uu > thr);
        eq += (uu == thr);
    }
    unsigned mypack = (gt << 16) | eq;
    unsigned p = warp_incl_scan(mypack, lane);
    if (lane == 31) wsum[w] = p;
    __syncthreads();
    unsigned off = 0;
#pragma unroll
    for (int i = 0; i < 8; i++)
        if (i < w) off += wsum[i];
    unsigned excl = p + off - mypack;
    unsigned gtb = excl >> 16, eqb = excl & 0xFFFFu;
    int bh = bhc >> 4;
#pragma unroll
    for (int r = 0; r < 16; r++) {
        unsigned uu = su[base + r];
        if (uu > thr) {
            unsigned emin = eqb < m ? eqb : m;
            int pos = (int)(gtb + emin);
            g_idx[(size_t)bhc * WSZc + pos] = base + r;
            atomicAdd(&g_cnt[bh * Tt + base + r], 1);
            gtb++;
        } else if (uu == thr) {
            if (eqb < m) {
                int pos = (int)(gtb + eqb);
                g_idx[(size_t)bhc * WSZc + pos] = base + r;
                atomicAdd(&g_cnt[bh * Tt + base + r], 1);
            }
            eqb++;
        }
    }
}

// ---------------- kernel 3: fp16 m16n8k16 tensor-core windowed attention -----
// 512 threads = 16 warps. SMSP-balanced tile permutation: warp w computes
// row-tile t = perm(w) so each SMSP's causal workload sums to exactly 68 units.
__device__ __forceinline__ unsigned pack2h(float lo, float hi) {
    unsigned u;
    asm("cvt.rn.f16x2.f32 %0, %1, %2;" : "=r"(u) : "f"(hi), "f"(lo));
    return u;
}
__device__ __forceinline__ unsigned short f2h(float f) {
    unsigned short h;
    asm("cvt.rn.f16.f32 %0, %1;" : "=h"(h) : "f"(f));
    return h;
}
__device__ __forceinline__ void mma16(float* d, const unsigned* a, uint2 b) {
    asm volatile("mma.sync.aligned.m16n8k16.row.col.f32.f16.f16.f32 "
                 "{%0,%1,%2,%3}, {%4,%5,%6,%7}, {%8,%9}, {%0,%1,%2,%3};"
                 : "+f"(d[0]), "+f"(d[1]), "+f"(d[2]), "+f"(d[3])
                 : "r"(a[0]), "r"(a[1]), "r"(a[2]), "r"(a[3]), "r"(b.x), "r"(b.y));
}

__device__ __forceinline__ void epi_vals(int t, int jc, int nt, int g, int c,
                                         float* s, float& l0, float& l1) {
    int i0 = 16 * t + g, i1 = i0 + 8;
    int j0 = 64 * jc + 8 * nt + 2 * c, j1 = j0 + 1;
    s[0] = (j0 > i0) ? 0.f : (j0 == i0) ? ((i0 == 0) ? 1.f : 0.f) : __expf(s[0] * 0.125f);
    s[1] = (j1 > i0) ? 0.f : (j1 == i0) ? 0.f : __expf(s[1] * 0.125f);
    s[2] = (j0 > i1) ? 0.f : (j0 == i1) ? 0.f : __expf(s[2] * 0.125f);
    s[3] = (j1 > i1) ? 0.f : (j1 == i1) ? 0.f : __expf(s[3] * 0.125f);
    l0 += s[0] + s[1];
    l1 += s[2] + s[3];
}

#define KV_BUF 2048                        // u32 per chunk per operand (fp16)
#define ATTN_SMEM_BYTES (8 * KV_BUF * 4)   // KF[4] + VF[4] = 64KB

__global__ void __launch_bounds__(512, 1) attn_kernel(const float* __restrict__ q,
                                                      const float* __restrict__ k,
                                                      const float* __restrict__ v,
                                                      float* __restrict__ out) {
    extern __shared__ unsigned smu[];  // [KF0..KF3, VF0..VF3]
    __shared__ int sidx[WSZc];

    int tid = threadIdx.x;
    int bhc = blockIdx.x;
    int bh = bhc >> 4;
    int w = tid >> 5, lane = tid & 31;
    int g = lane >> 2, c = lane & 3;

    // SMSP-balanced permutation: quads {0,1,2,3},{7,6,5,4},{8,9,10,11},{15,14,13,12}
    int t = 4 * (w >> 2) + (((w >> 2) & 1) ? (3 - (w & 3)) : (w & 3));

    if (tid < WSZc) sidx[tid] = g_idx[(size_t)bhc * WSZc + tid];
    __syncthreads();

    // ---- staging: threads 0-255 K (normalize in-thread), 256-511 V ----
    if (tid < 256) {
        int gj = sidx[tid];
        int jcc = tid >> 6, r = tid & 63;
        const float4* ks4 = (const float4*)(k + ((size_t)bh * Tt + gj) * Dd);
        unsigned* KF = smu + jcc * KV_BUF;
        int nt = r >> 3, gk = r & 7;
        float4 kv[16];
        float ss = 0.f;
#pragma unroll
        for (int e = 0; e < 16; e++) {
            kv[e] = ks4[e];
            ss += kv[e].x * kv[e].x + kv[e].y * kv[e].y +
                  kv[e].z * kv[e].z + kv[e].w * kv[e].w;
        }
        float inv = rsqrtf(ss);
        // KF B-frag: reg0 = {kn[16ks+2c], kn[16ks+2c+1]}, reg1 = d+8
#pragma unroll
        for (int ks = 0; ks < 4; ks++) {
#pragma unroll
            for (int cc = 0; cc < 4; cc++) {
                int e0 = 4 * ks + (cc >> 1);
                float lo0, hi0, lo1, hi1;
                if (cc & 1) {
                    lo0 = kv[e0].z; hi0 = kv[e0].w;
                    lo1 = kv[e0 + 2].z; hi1 = kv[e0 + 2].w;
                } else {
                    lo0 = kv[e0].x; hi0 = kv[e0].y;
                    lo1 = kv[e0 + 2].x; hi1 = kv[e0 + 2].y;
                }
                unsigned r0 = pack2h(lo0 * inv, hi0 * inv);
                unsigned r1 = pack2h(lo1 * inv, hi1 * inv);
                *(uint2*)&KF[((ks * 8 + nt) * 32 + gk * 4 + cc) * 2] = make_uint2(r0, r1);
            }
        }
    } else {
        int rr = tid - 256;
        int gj = sidx[rr];
        int jcc = rr >> 6, r = rr & 63;
        const float4* vs4 = (const float4*)(v + ((size_t)bh * Tt + gj) * Dd);
        unsigned short* VH = (unsigned short*)(smu + 4 * KV_BUF + jcc * KV_BUF);
        // key r within chunk: kg = r>>4, position-in-16: reg*8 + 2c + p
        int kg = r >> 4, rloc = r & 15;
        int reg = (rloc >> 3) & 1, cc = (rloc & 7) >> 1, p = rloc & 1;
#pragma unroll
        for (int e = 0; e < 16; e++) {
            float4 vv = vs4[e];
            float vals[4] = {vv.x, vv.y, vv.z, vv.w};
#pragma unroll
            for (int j = 0; j < 4; j++) {
                int d = e * 4 + j;
                int nt2 = d >> 3, gv = d & 7;
                int addr32 = ((kg * 8 + nt2) * 32 + gv * 4 + cc) * 2 + reg;
                VH[addr32 * 2 + p] = f2h(vals[j]);
            }
        }
    }

    // ---- Q A-fragments (fp16) into registers (warp w owns tile t) ----
    unsigned A[4][4];
    {
        const float* qb = q + (size_t)bh * Tt * Dd;
        const float* r0 = qb + (size_t)sidx[16 * t + g] * Dd;
        const float* r1 = qb + (size_t)sidx[16 * t + g + 8] * Dd;
#pragma unroll
        for (int ks = 0; ks < 4; ks++) {
            int d0 = 16 * ks + 2 * c;
            A[ks][0] = pack2h(r0[d0], r0[d0 + 1]);
            A[ks][1] = pack2h(r1[d0], r1[d0 + 1]);
            A[ks][2] = pack2h(r0[d0 + 8], r0[d0 + 9]);
            A[ks][3] = pack2h(r1[d0 + 8], r1[d0 + 9]);
        }
    }

    float O[8][4];
#pragma unroll
    for (int nt = 0; nt < 8; nt++)
#pragma unroll
        for (int r = 0; r < 4; r++) O[nt][r] = 0.f;
    float lp[2] = {0.f, 0.f};

    __syncthreads();   // the ONLY mainloop barrier

    for (int jc = 0; jc < 4; jc++) {
        int lim = 2 * t + 1 - 8 * jc;
        if (lim < 0) break;
        const unsigned* KF = smu + jc * KV_BUF;
        const unsigned* VF = smu + 4 * KV_BUF + jc * KV_BUF;

#pragma unroll
        for (int nt = 0; nt < 8; nt += 2) {
            if (nt > lim) break;
            bool two = (nt + 1 <= lim);
            float sa[4] = {0.f, 0.f, 0.f, 0.f};  // nt,   ks 0-1
            float sb[4] = {0.f, 0.f, 0.f, 0.f};  // nt,   ks 2-3
            float sc[4] = {0.f, 0.f, 0.f, 0.f};  // nt+1, ks 0-1
            float sd[4] = {0.f, 0.f, 0.f, 0.f};  // nt+1, ks 2-3
#pragma unroll
            for (int ks = 0; ks < 2; ks++) {
                uint2 b0 = *(const uint2*)&KF[((ks * 8 + nt) * 32 + lane) * 2];
                uint2 b1 = *(const uint2*)&KF[(((ks + 2) * 8 + nt) * 32 + lane) * 2];
                mma16(sa, A[ks], b0);
                mma16(sb, A[ks + 2], b1);
                if (two) {
                    uint2 b2 = *(const uint2*)&KF[((ks * 8 + nt + 1) * 32 + lane) * 2];
                    uint2 b3 = *(const uint2*)&KF[(((ks + 2) * 8 + nt + 1) * 32 + lane) * 2];
                    mma16(sc, A[ks], b2);
                    mma16(sd, A[ks + 2], b3);
                }
            }
#pragma unroll
            for (int r = 0; r < 4; r++) { sa[r] += sb[r]; sc[r] += sd[r]; }

            epi_vals(t, jc, nt, g, c, sa, lp[0], lp[1]);
            if (two) epi_vals(t, jc, nt + 1, g, c, sc, lp[0], lp[1]);
            // else sc stays all-zero -> contributes nothing

            // P 16x16 A-fragment = the two accumulators packed (no shuffles)
            unsigned P[4];
            P[0] = pack2h(sa[0], sa[1]);
            P[1] = pack2h(sa[2], sa[3]);
            P[2] = pack2h(sc[0], sc[1]);
            P[3] = pack2h(sc[2], sc[3]);

            int kg = nt >> 1;
#pragma unroll
            for (int nt2 = 0; nt2 < 8; nt2++) {
                uint2 bv = *(const uint2*)&VF[((kg * 8 + nt2) * 32 + lane) * 2];
                mma16(O[nt2], P, bv);
            }
        }
    }

    // ---- row-sum reduce across quad, normalize, scatter ----
    float rs[2];
#pragma unroll
    for (int hf = 0; hf < 2; hf++) {
        float s = lp[hf];
        s += __shfl_xor_sync(0xffffffffu, s, 1);
        s += __shfl_xor_sync(0xffffffffu, s, 2);
        rs[hf] = 1.f / s;
    }
    {
        float* ob = out + (size_t)bh * Tt * Dd;
        float* o0 = ob + (size_t)sidx[16 * t + g] * Dd;
        float* o1 = ob + (size_t)sidx[16 * t + g + 8] * Dd;
#pragma unroll
        for (int nt2 = 0; nt2 < 8; nt2++) {
            int col = 8 * nt2 + 2 * c;
            atomicAdd(o0 + col, O[nt2][0] * rs[0]);
            atomicAdd(o0 + col + 1, O[nt2][1] * rs[0]);
            atomicAdd(o1 + col, O[nt2][2] * rs[1]);
            atomicAdd(o1 + col + 1, O[nt2][3] * rs[1]);
        }
    }
}

// ---------------- kernel 4: divide by count + aux loss ----------------
__global__ void finalize_kernel(float* out, int out_size) {
    const int n = Bq * Hh * Tt * Dd;
    const int n4 = n / 4;
    int i = blockIdx.x * blockDim.x + threadIdx.x;
    int stride = gridDim.x * blockDim.x;
    for (int p = i; p < n4; p += stride) {
        float4 o = ((float4*)out)[p];
        float cc = (float)g_cnt[p >> 4];
        float inv = 1.f / (cc + 1e-5f);
        o.x *= inv; o.y *= inv; o.z *= inv; o.w *= inv;
        ((float4*)out)[p] = o;
    }
    if (blockIdx.x == 0) {
        __shared__ float sred[256];
        float s = 0.f;
        for (int p = threadIdx.x; p < Bq * Hh * Tt / 8; p += 256) s += g_aux_part[p];
        sred[threadIdx.x] = s;
        __syncthreads();
        for (int off = 128; off; off >>= 1) {
            if (threadIdx.x < off) sred[threadIdx.x] += sred[threadIdx.x + off];
            __syncthreads();
        }
        if (threadIdx.x == 0 && out_size > n)
            out[n] = sred[0] * (1e-4f / (float)n);
    }
}

// ---------------- launch ----------------
extern "C" void kernel_launch(void* const* d_in, const int* in_sizes, int n_in,
                              void* d_out, int out_size) {
    const float* q = (const float*)d_in[0];
    const float* k = (const float*)d_in[1];
    const float* v = (const float*)d_in[2];
    const float* means = (const float*)d_in[3];
    float* out = (float*)d_out;

    cudaFuncSetAttribute(attn_kernel, cudaFuncAttributeMaxDynamicSharedMemorySize,
                         ATTN_SMEM_BYTES);

    route_kernel<<<Bq * Hh * Tt / 8, 256>>>(k, means);
    topk_kernel<<<Bq * Hh * NCc, 256>>>(out);
    attn_kernel<<<Bq * Hh * NCc, 512, ATTN_SMEM_BYTES>>>(q, k, v, out);
    finalize_kernel<<<2048, 256>>>(out, out_size);
}